// round 15
// baseline (speedup 1.0000x reference)
#include <cuda_runtime.h>
#include <cuda_fp16.h>

#define N_USERS    50000
#define N_ENTITIES 100000
#define CHANNEL    64
#define N_FACTORS  4
#define N_RELM1    8
#define N_EDGES    1500000
#define NNZ        800000

#define NBINS   (N_ENTITIES + N_USERS)
#define NITEMS  (N_EDGES + NNZ)
#define CHUNK   1024
#define NBLK    ((NBINS + CHUNK - 1) / CHUNK)   // 147

#define EV4 (N_ENTITIES * 16)
#define UV4 (N_USERS * 16)

#define HOP_BLOCKS 1184   // ~148 SMs x 8 resident 256-thread blocks

// fp16 ping-pong entity tables: one row = 64ch = 32 x half2 = 128B = 1 L2 line
__device__ __half2 g_eh0[N_ENTITIES * 32];
__device__ __half2 g_eh1[N_ENTITIES * 32];
// normalized user rows after hop0 (fp32)
__device__ float2  g_un[N_USERS * 32];
__device__ float   g_disen[N_FACTORS * CHANNEL];

// CSR build (g_cnt zero-initialized; re-zeroed by k_scan3 each replay)
__device__ int   g_cnt[NBINS];
__device__ int   g_off[NBINS + 1];
__device__ int   g_pos[NBINS];
__device__ int   g_bsum[NBLK];
__device__ int   g_bpre[NBLK];
__device__ int   g_ecol[N_EDGES];   // tail | (rel<<20)
__device__ int2  g_uitem[NNZ];      // {col, val bits}

// ---------------------------------------------------------------------------
// init: convert entity table to fp16, seed outputs with the raw embeddings
// ---------------------------------------------------------------------------
__global__ void k_init(const float4* __restrict__ ent, const float4* __restrict__ usr,
                       float4* __restrict__ out_ent, float4* __restrict__ out_usr) {
    int i = blockIdx.x * blockDim.x + threadIdx.x;
    if (i < EV4) {
        float4 v = ent[i];
        out_ent[i] = v;
        g_eh0[i * 2 + 0] = __floats2half2_rn(v.x, v.y);
        g_eh0[i * 2 + 1] = __floats2half2_rn(v.z, v.w);
    } else {
        int j = i - EV4;
        if (j < UV4) out_usr[j] = usr[j];
    }
}

// ---------------------------------------------------------------------------
__global__ void k_hist(const int* __restrict__ head, const int* __restrict__ irows) {
    int i = blockIdx.x * blockDim.x + threadIdx.x;
    if (i < N_EDGES) {
        atomicAdd(&g_cnt[head[i]], 1);
    } else if (i < NITEMS) {
        atomicAdd(&g_cnt[N_ENTITIES + irows[i - N_EDGES]], 1);
    }
}

__global__ void k_scan1() {
    __shared__ int s[CHUNK];
    int b = blockIdx.x, t = threadIdx.x;
    int i = b * CHUNK + t;
    s[t] = (i < NBINS) ? g_cnt[i] : 0;
    __syncthreads();
    for (int o = CHUNK >> 1; o; o >>= 1) {
        if (t < o) s[t] += s[t + o];
        __syncthreads();
    }
    if (t == 0) g_bsum[b] = s[0];
}

__global__ void k_scan2() {
    __shared__ int s[256];
    int t = threadIdx.x;
    int v = (t < NBLK) ? g_bsum[t] : 0;
    s[t] = v;
    __syncthreads();
    for (int o = 1; o < 256; o <<= 1) {
        int x = (t >= o) ? s[t - o] : 0;
        __syncthreads();
        s[t] += x;
        __syncthreads();
    }
    if (t < NBLK) g_bpre[t] = s[t] - v;
}

// scan + write offsets/cursors; sentinel; re-zero g_cnt for the next replay
__global__ void k_scan3() {
    __shared__ int s[CHUNK];
    int b = blockIdx.x, t = threadIdx.x;
    int i = b * CHUNK + t;
    int v = (i < NBINS) ? g_cnt[i] : 0;
    s[t] = v;
    __syncthreads();
    for (int o = 1; o < CHUNK; o <<= 1) {
        int x = (t >= o) ? s[t - o] : 0;
        __syncthreads();
        s[t] += x;
        __syncthreads();
    }
    if (i < NBINS) {
        int off = g_bpre[b] + s[t] - v;
        g_off[i] = off;
        g_pos[i] = off;
        g_cnt[i] = 0;
    }
    if (i == NBINS - 1) g_off[NBINS] = NITEMS;
}

__global__ void k_scatter(const int* __restrict__ head, const int* __restrict__ tail,
                          const int* __restrict__ etype,
                          const int* __restrict__ irows, const int* __restrict__ icols,
                          const float* __restrict__ ivals) {
    int i = blockIdx.x * blockDim.x + threadIdx.x;
    if (i < N_EDGES) {
        int h = head[i];
        int pos = atomicAdd(&g_pos[h], 1);
        g_ecol[pos] = tail[i] | ((etype[i] - 1) << 20);
    } else if (i < NITEMS) {
        int j = i - N_EDGES;
        int r = irows[j];
        int pos = atomicAdd(&g_pos[N_ENTITIES + r], 1) - N_EDGES;
        g_uitem[pos] = make_int2(icols[j], __float_as_int(ivals[j]));
    }
}

// ---------------------------------------------------------------------------
// small kernel: disen = softmax(att) @ W + warp-parallel distance correlation
// ---------------------------------------------------------------------------
__global__ void k_small(const float* __restrict__ att, const float* __restrict__ w,
                        float* __restrict__ out_cor) {
    __shared__ float s_cor[6];
    int t = threadIdx.x;

    if (t < N_FACTORS * CHANNEL) {
        int f = t >> 6, c = t & 63;
        float row[N_RELM1];
        float mx = -1e30f;
        for (int j = 0; j < N_RELM1; j++) { row[j] = att[f * N_RELM1 + j]; mx = fmaxf(mx, row[j]); }
        float s = 0.f;
        for (int j = 0; j < N_RELM1; j++) { row[j] = expf(row[j] - mx); s += row[j]; }
        float invs = 1.f / s;
        float acc = 0.f;
        for (int j = 0; j < N_RELM1; j++) acc += row[j] * invs * w[j * CHANNEL + c];
        g_disen[t] = acc;
    }

    int wid = t >> 5, lane = t & 31;
    if (wid < 6) {
        const int pi_[6] = {0, 0, 0, 1, 1, 2};
        const int pj_[6] = {1, 2, 3, 2, 3, 3};
        int p1 = pi_[wid], p2 = pj_[wid];
        float t1[N_RELM1], t2[N_RELM1];
        #pragma unroll
        for (int k = 0; k < N_RELM1; k++) {
            t1[k] = __ldg(&att[p1 * N_RELM1 + k]);
            t2[k] = __ldg(&att[p2 * N_RELM1 + k]);
        }
        int i1 = lane >> 3, j1 = lane & 7, i2 = i1 + 4;
        float da1 = t1[i1] - t1[j1], da2 = t1[i2] - t1[j1];
        float db1 = t2[i1] - t2[j1], db2 = t2[i2] - t2[j1];
        float a1 = sqrtf(da1 * da1 + 1e-8f), a2 = sqrtf(da2 * da2 + 1e-8f);
        float b1 = sqrtf(db1 * db1 + 1e-8f), b2 = sqrtf(db2 * db2 + 1e-8f);

        float ar1 = a1, ar2 = a2, br1 = b1, br2 = b2;
        #pragma unroll
        for (int o = 1; o <= 4; o <<= 1) {
            ar1 += __shfl_xor_sync(0xFFFFFFFFu, ar1, o);
            ar2 += __shfl_xor_sync(0xFFFFFFFFu, ar2, o);
            br1 += __shfl_xor_sync(0xFFFFFFFFu, br1, o);
            br2 += __shfl_xor_sync(0xFFFFFFFFu, br2, o);
        }
        float ac1 = a1, ac2 = a2, bc1 = b1, bc2 = b2;
        #pragma unroll
        for (int o = 8; o <= 16; o <<= 1) {
            ac1 += __shfl_xor_sync(0xFFFFFFFFu, ac1, o);
            ac2 += __shfl_xor_sync(0xFFFFFFFFu, ac2, o);
            bc1 += __shfl_xor_sync(0xFFFFFFFFu, bc1, o);
            bc2 += __shfl_xor_sync(0xFFFFFFFFu, bc2, o);
        }
        float asum = a1 + a2, bsum = b1 + b2;
        #pragma unroll
        for (int o = 1; o <= 16; o <<= 1) {
            asum += __shfl_xor_sync(0xFFFFFFFFu, asum, o);
            bsum += __shfl_xor_sync(0xFFFFFFFFu, bsum, o);
        }
        float am = asum * (1.f / 64.f), bm = bsum * (1.f / 64.f);
        float acm = (ac1 + ac2) * 0.125f, bcm = (bc1 + bc2) * 0.125f;
        float A1 = a1 - acm - ar1 * 0.125f + am;
        float A2 = a2 - acm - ar2 * 0.125f + am;
        float B1 = b1 - bcm - br1 * 0.125f + bm;
        float B2 = b2 - bcm - br2 * 0.125f + bm;
        float sAB = A1 * B1 + A2 * B2;
        float sAA = A1 * A1 + A2 * A2;
        float sBB = B1 * B1 + B2 * B2;
        #pragma unroll
        for (int o = 1; o <= 16; o <<= 1) {
            sAB += __shfl_xor_sync(0xFFFFFFFFu, sAB, o);
            sAA += __shfl_xor_sync(0xFFFFFFFFu, sAA, o);
            sBB += __shfl_xor_sync(0xFFFFFFFFu, sBB, o);
        }
        if (lane == 0) {
            float dAB = sqrtf(fmaxf(sAB * (1.f / 64.f), 0.f) + 1e-8f);
            float dAA = sqrtf(fmaxf(sAA * (1.f / 64.f), 0.f) + 1e-8f);
            float dBB = sqrtf(fmaxf(sBB * (1.f / 64.f), 0.f) + 1e-8f);
            s_cor[wid] = dAB / sqrtf(dAA * dBB + 1e-8f);
        }
    }
    __syncthreads();
    if (t == 0)
        *out_cor = s_cor[0] + s_cor[1] + s_cor[2] + s_cor[3] + s_cor[4] + s_cor[5];
}

// ---------------------------------------------------------------------------
// fused hop: warp-per-destination with GRID-STRIDE warp loop (load balance —
// each warp handles ~16 strided destinations, averaging degree variance so
// blocks don't idle on their slowest warp). Inner loops identical to R13.
// ---------------------------------------------------------------------------
__global__ void k_hop(int hop, const float2* __restrict__ user_emb,
                      const float* __restrict__ weight,
                      const float2* __restrict__ latent2,
                      float2* __restrict__ out_ent, float2* __restrict__ out_usr) {
    __shared__ float2 s_w[N_RELM1 * 32];

    int tid = threadIdx.x;
    for (int i = tid; i < N_RELM1 * 32; i += blockDim.x)
        s_w[i] = ((const float2*)weight)[i];
    __syncthreads();

    int lane = tid & 31;
    int warp0 = (blockIdx.x * blockDim.x + tid) >> 5;
    int nwarps = (gridDim.x * blockDim.x) >> 5;

    const __half2* ecur = hop ? g_eh1 : g_eh0;
    __half2*       enxt = hop ? g_eh0 : g_eh1;

    for (int gw = warp0; gw < NBINS; gw += nwarps) {
        int start = g_off[gw];
        int n     = g_off[gw + 1] - start;

        if (gw < N_ENTITIES) {
            float2 acc = make_float2(0.f, 0.f);
            #pragma unroll 4
            for (int k = 0; k < n; k++) {
                int p = __ldg(&g_ecol[start + k]);
                int t = p & 0xFFFFF;
                int r = p >> 20;
                float2 e = __half22float2(__ldg(&ecur[t * 32 + lane]));
                float2 w = s_w[r * 32 + lane];
                acc.x = fmaf(e.x, w.x, acc.x);
                acc.y = fmaf(e.y, w.y, acc.y);
            }
            float ss = acc.x * acc.x + acc.y * acc.y;
            #pragma unroll
            for (int o = 16; o; o >>= 1) ss += __shfl_xor_sync(0xFFFFFFFFu, ss, o);
            float inv = 1.f / fmaxf(sqrtf(ss), 1e-12f);
            acc.x *= inv; acc.y *= inv;
            int idx = gw * 32 + lane;
            enxt[idx] = __floats2half2_rn(acc.x, acc.y);
            float2 o = out_ent[idx];
            o.x += acc.x; o.y += acc.y;
            out_ent[idx] = o;
        } else {
            int u = gw - N_ENTITIES;
            int ustart = start - N_EDGES;
            float2 acc = make_float2(0.f, 0.f);
            #pragma unroll 4
            for (int k = 0; k < n; k++) {
                int2 it = __ldg(&g_uitem[ustart + k]);
                float v = __int_as_float(it.y);
                float2 e = __half22float2(__ldg(&ecur[it.x * 32 + lane]));
                acc.x = fmaf(v, e.x, acc.x);
                acc.y = fmaf(v, e.y, acc.y);
            }
            int idx = u * 32 + lane;
            float2 uc = hop ? g_un[idx] : user_emb[idx];
            float d[N_FACTORS];
            #pragma unroll
            for (int f = 0; f < N_FACTORS; f++) {
                float2 lf = __ldg(&latent2[f * 32 + lane]);
                float p = uc.x * lf.x + uc.y * lf.y;
                #pragma unroll
                for (int o = 16; o; o >>= 1) p += __shfl_xor_sync(0xFFFFFFFFu, p, o);
                d[f] = p;
            }
            float mx = fmaxf(fmaxf(d[0], d[1]), fmaxf(d[2], d[3]));
            float s[N_FACTORS], sum = 0.f;
            #pragma unroll
            for (int f = 0; f < N_FACTORS; f++) { s[f] = expf(d[f] - mx); sum += s[f]; }
            float invs = 1.f / sum;
            const float2* dw = (const float2*)g_disen;
            float2 mix = make_float2(0.f, 0.f);
            #pragma unroll
            for (int f = 0; f < N_FACTORS; f++) {
                float sf = s[f] * invs;
                float2 w2 = dw[f * 32 + lane];
                mix.x = fmaf(sf, w2.x, mix.x);
                mix.y = fmaf(sf, w2.y, mix.y);
            }
            float2 un = make_float2(acc.x * (mix.x + 1.f), acc.y * (mix.y + 1.f));
            float ss = un.x * un.x + un.y * un.y;
            #pragma unroll
            for (int o = 16; o; o >>= 1) ss += __shfl_xor_sync(0xFFFFFFFFu, ss, o);
            float inv = 1.f / fmaxf(sqrtf(ss), 1e-12f);
            un.x *= inv; un.y *= inv;
            g_un[idx] = un;
            float2 o = out_usr[idx];
            o.x += un.x; o.y += un.y;
            out_usr[idx] = o;
        }
    }
}

// ---------------------------------------------------------------------------
extern "C" void kernel_launch(void* const* d_in, const int* in_sizes, int n_in,
                              void* d_out, int out_size) {
    const float* user_emb   = (const float*)d_in[0];
    const float* entity_emb = (const float*)d_in[1];
    const float* latent_emb = (const float*)d_in[2];
    const float* weight     = (const float*)d_in[3];
    const float* att        = (const float*)d_in[4];
    const float* ivals      = (const float*)d_in[5];
    const int*   head       = (const int*)d_in[6];
    const int*   tail       = (const int*)d_in[7];
    const int*   etype      = (const int*)d_in[8];
    const int*   irows      = (const int*)d_in[9];
    const int*   icols      = (const int*)d_in[10];

    float* out     = (float*)d_out;
    float* out_ent = out;
    float* out_usr = out + (size_t)N_ENTITIES * CHANNEL;
    float* out_cor = out + (size_t)(N_ENTITIES + N_USERS) * CHANNEL;

    const int TPB = 256;
    int init_blocks = (EV4 + UV4 + TPB - 1) / TPB;
    int item_blocks = (NITEMS + TPB - 1) / TPB;

    k_init<<<init_blocks, TPB>>>((const float4*)entity_emb, (const float4*)user_emb,
                                 (float4*)out_ent, (float4*)out_usr);
    k_small<<<1, 256>>>(att, weight, out_cor);

    k_hist<<<item_blocks, TPB>>>(head, irows);
    k_scan1<<<NBLK, CHUNK>>>();
    k_scan2<<<1, 256>>>();
    k_scan3<<<NBLK, CHUNK>>>();
    k_scatter<<<item_blocks, TPB>>>(head, tail, etype, irows, icols, ivals);

    k_hop<<<HOP_BLOCKS, TPB>>>(0, (const float2*)user_emb, weight,
                               (const float2*)latent_emb,
                               (float2*)out_ent, (float2*)out_usr);
    k_hop<<<HOP_BLOCKS, TPB>>>(1, (const float2*)user_emb, weight,
                               (const float2*)latent_emb,
                               (float2*)out_ent, (float2*)out_usr);
}

// round 16
// speedup vs baseline: 1.0797x; 1.0797x over previous
#include <cuda_runtime.h>
#include <cuda_fp16.h>

#define N_USERS    50000
#define N_ENTITIES 100000
#define CHANNEL    64
#define N_FACTORS  4
#define N_RELM1    8
#define N_EDGES    1500000
#define NNZ        800000

#define NBINS   (N_ENTITIES + N_USERS)
#define NITEMS  (N_EDGES + NNZ)
#define CHUNK   1024
#define NBLK    ((NBINS + CHUNK - 1) / CHUNK)   // 147

#define EV4 (N_ENTITIES * 16)
#define UV4 (N_USERS * 16)

// fp16 ping-pong entity tables: one row = 64ch = 32 x half2 = 128B = 1 L2 line
__device__ __half2 g_eh0[N_ENTITIES * 32];
__device__ __half2 g_eh1[N_ENTITIES * 32];
// normalized user rows after hop0 (fp32)
__device__ float2  g_un[N_USERS * 32];
__device__ float   g_disen[N_FACTORS * CHANNEL];

// CSR build (g_cnt zero-initialized; re-zeroed by k_scan3 each replay)
__device__ int   g_cnt[NBINS];
__device__ int   g_off[NBINS + 1];
__device__ int   g_pos[NBINS];
__device__ int   g_bsum[NBLK];
__device__ int   g_ecol[N_EDGES];   // tail | (rel<<20)
__device__ int2  g_uitem[NNZ];      // {col, val bits}

// ---------------------------------------------------------------------------
// init: convert entity table to fp16, seed outputs with the raw embeddings
// ---------------------------------------------------------------------------
__global__ void k_init(const float4* __restrict__ ent, const float4* __restrict__ usr,
                       float4* __restrict__ out_ent, float4* __restrict__ out_usr) {
    int i = blockIdx.x * blockDim.x + threadIdx.x;
    if (i < EV4) {
        float4 v = ent[i];
        out_ent[i] = v;
        g_eh0[i * 2 + 0] = __floats2half2_rn(v.x, v.y);
        g_eh0[i * 2 + 1] = __floats2half2_rn(v.z, v.w);
    } else {
        int j = i - EV4;
        if (j < UV4) out_usr[j] = usr[j];
    }
}

// ---------------------------------------------------------------------------
__global__ void k_hist(const int* __restrict__ head, const int* __restrict__ irows) {
    int i = blockIdx.x * blockDim.x + threadIdx.x;
    if (i < N_EDGES) {
        atomicAdd(&g_cnt[head[i]], 1);
    } else if (i < NITEMS) {
        atomicAdd(&g_cnt[N_ENTITIES + irows[i - N_EDGES]], 1);
    }
}

__global__ void k_scan1() {
    __shared__ int s[CHUNK];
    int b = blockIdx.x, t = threadIdx.x;
    int i = b * CHUNK + t;
    s[t] = (i < NBINS) ? g_cnt[i] : 0;
    __syncthreads();
    for (int o = CHUNK >> 1; o; o >>= 1) {
        if (t < o) s[t] += s[t + o];
        __syncthreads();
    }
    if (t == 0) g_bsum[b] = s[0];
}

// per-chunk scan; block base computed inline from g_bsum (scan2 folded in);
// writes offsets + cursors, sentinel, re-zeros g_cnt for the next replay
__global__ void k_scan3() {
    __shared__ int s[CHUNK];
    __shared__ int sb[256];
    int b = blockIdx.x, t = threadIdx.x;

    // inline exclusive prefix of g_bsum (147 values), redundant per block
    if (t < 256) sb[t] = (t < NBLK) ? g_bsum[t] : 0;
    __syncthreads();
    for (int o = 1; o < 256; o <<= 1) {
        int x = (t < 256 && t >= o) ? sb[t - o] : 0;
        __syncthreads();
        if (t < 256) sb[t] += x;
        __syncthreads();
    }
    int base = sb[b] - g_bsum[b];   // exclusive prefix for this block

    int i = b * CHUNK + t;
    int v = (i < NBINS) ? g_cnt[i] : 0;
    s[t] = v;
    __syncthreads();
    for (int o = 1; o < CHUNK; o <<= 1) {
        int x = (t >= o) ? s[t - o] : 0;
        __syncthreads();
        s[t] += x;
        __syncthreads();
    }
    if (i < NBINS) {
        int off = base + s[t] - v;
        g_off[i] = off;
        g_pos[i] = off;
        g_cnt[i] = 0;
    }
    if (i == NBINS - 1) g_off[NBINS] = NITEMS;
}

__global__ void k_scatter(const int* __restrict__ head, const int* __restrict__ tail,
                          const int* __restrict__ etype,
                          const int* __restrict__ irows, const int* __restrict__ icols,
                          const float* __restrict__ ivals) {
    int i = blockIdx.x * blockDim.x + threadIdx.x;
    if (i < N_EDGES) {
        int h = head[i];
        int pos = atomicAdd(&g_pos[h], 1);
        g_ecol[pos] = tail[i] | ((etype[i] - 1) << 20);
    } else if (i < NITEMS) {
        int j = i - N_EDGES;
        int r = irows[j];
        int pos = atomicAdd(&g_pos[N_ENTITIES + r], 1) - N_EDGES;
        g_uitem[pos] = make_int2(icols[j], __float_as_int(ivals[j]));
    }
}

// ---------------------------------------------------------------------------
// small kernel: disen = softmax(att) @ W + warp-parallel distance correlation
// ---------------------------------------------------------------------------
__global__ void k_small(const float* __restrict__ att, const float* __restrict__ w,
                        float* __restrict__ out_cor) {
    __shared__ float s_cor[6];
    int t = threadIdx.x;

    if (t < N_FACTORS * CHANNEL) {
        int f = t >> 6, c = t & 63;
        float row[N_RELM1];
        float mx = -1e30f;
        for (int j = 0; j < N_RELM1; j++) { row[j] = att[f * N_RELM1 + j]; mx = fmaxf(mx, row[j]); }
        float s = 0.f;
        for (int j = 0; j < N_RELM1; j++) { row[j] = expf(row[j] - mx); s += row[j]; }
        float invs = 1.f / s;
        float acc = 0.f;
        for (int j = 0; j < N_RELM1; j++) acc += row[j] * invs * w[j * CHANNEL + c];
        g_disen[t] = acc;
    }

    int wid = t >> 5, lane = t & 31;
    if (wid < 6) {
        const int pi_[6] = {0, 0, 0, 1, 1, 2};
        const int pj_[6] = {1, 2, 3, 2, 3, 3};
        int p1 = pi_[wid], p2 = pj_[wid];
        float t1[N_RELM1], t2[N_RELM1];
        #pragma unroll
        for (int k = 0; k < N_RELM1; k++) {
            t1[k] = __ldg(&att[p1 * N_RELM1 + k]);
            t2[k] = __ldg(&att[p2 * N_RELM1 + k]);
        }
        int i1 = lane >> 3, j1 = lane & 7, i2 = i1 + 4;
        float da1 = t1[i1] - t1[j1], da2 = t1[i2] - t1[j1];
        float db1 = t2[i1] - t2[j1], db2 = t2[i2] - t2[j1];
        float a1 = sqrtf(da1 * da1 + 1e-8f), a2 = sqrtf(da2 * da2 + 1e-8f);
        float b1 = sqrtf(db1 * db1 + 1e-8f), b2 = sqrtf(db2 * db2 + 1e-8f);

        float ar1 = a1, ar2 = a2, br1 = b1, br2 = b2;
        #pragma unroll
        for (int o = 1; o <= 4; o <<= 1) {
            ar1 += __shfl_xor_sync(0xFFFFFFFFu, ar1, o);
            ar2 += __shfl_xor_sync(0xFFFFFFFFu, ar2, o);
            br1 += __shfl_xor_sync(0xFFFFFFFFu, br1, o);
            br2 += __shfl_xor_sync(0xFFFFFFFFu, br2, o);
        }
        float ac1 = a1, ac2 = a2, bc1 = b1, bc2 = b2;
        #pragma unroll
        for (int o = 8; o <= 16; o <<= 1) {
            ac1 += __shfl_xor_sync(0xFFFFFFFFu, ac1, o);
            ac2 += __shfl_xor_sync(0xFFFFFFFFu, ac2, o);
            bc1 += __shfl_xor_sync(0xFFFFFFFFu, bc1, o);
            bc2 += __shfl_xor_sync(0xFFFFFFFFu, bc2, o);
        }
        float asum = a1 + a2, bsum = b1 + b2;
        #pragma unroll
        for (int o = 1; o <= 16; o <<= 1) {
            asum += __shfl_xor_sync(0xFFFFFFFFu, asum, o);
            bsum += __shfl_xor_sync(0xFFFFFFFFu, bsum, o);
        }
        float am = asum * (1.f / 64.f), bm = bsum * (1.f / 64.f);
        float acm = (ac1 + ac2) * 0.125f, bcm = (bc1 + bc2) * 0.125f;
        float A1 = a1 - acm - ar1 * 0.125f + am;
        float A2 = a2 - acm - ar2 * 0.125f + am;
        float B1 = b1 - bcm - br1 * 0.125f + bm;
        float B2 = b2 - bcm - br2 * 0.125f + bm;
        float sAB = A1 * B1 + A2 * B2;
        float sAA = A1 * A1 + A2 * A2;
        float sBB = B1 * B1 + B2 * B2;
        #pragma unroll
        for (int o = 1; o <= 16; o <<= 1) {
            sAB += __shfl_xor_sync(0xFFFFFFFFu, sAB, o);
            sAA += __shfl_xor_sync(0xFFFFFFFFu, sAA, o);
            sBB += __shfl_xor_sync(0xFFFFFFFFu, sBB, o);
        }
        if (lane == 0) {
            float dAB = sqrtf(fmaxf(sAB * (1.f / 64.f), 0.f) + 1e-8f);
            float dAA = sqrtf(fmaxf(sAA * (1.f / 64.f), 0.f) + 1e-8f);
            float dBB = sqrtf(fmaxf(sBB * (1.f / 64.f), 0.f) + 1e-8f);
            s_cor[wid] = dAB / sqrtf(dAA * dBB + 1e-8f);
        }
    }
    __syncthreads();
    if (t == 0)
        *out_cor = s_cor[0] + s_cor[1] + s_cor[2] + s_cor[3] + s_cor[4] + s_cor[5];
}

// ---------------------------------------------------------------------------
// entity hop: warp-per-entity, R13 inner loop verbatim. Lean register set
// (no softmax state) -> higher occupancy for the dominant 1.5M-edge pass.
// ---------------------------------------------------------------------------
__global__ void k_hop_ent(int hop, const float* __restrict__ weight,
                          const float2* __restrict__ out_seed_unused,
                          float2* __restrict__ out_ent) {
    __shared__ float2 s_w[N_RELM1 * 32];
    int tid = threadIdx.x;
    for (int i = tid; i < N_RELM1 * 32; i += blockDim.x)
        s_w[i] = ((const float2*)weight)[i];
    __syncthreads();

    int gw   = (blockIdx.x * blockDim.x + tid) >> 5;
    int lane = tid & 31;
    if (gw >= N_ENTITIES) return;

    const __half2* ecur = hop ? g_eh1 : g_eh0;
    __half2*       enxt = hop ? g_eh0 : g_eh1;

    int start = g_off[gw];
    int n     = g_off[gw + 1] - start;

    float2 acc = make_float2(0.f, 0.f);
    #pragma unroll 4
    for (int k = 0; k < n; k++) {
        int p = __ldg(&g_ecol[start + k]);
        int t = p & 0xFFFFF;
        int r = p >> 20;
        float2 e = __half22float2(__ldg(&ecur[t * 32 + lane]));
        float2 w = s_w[r * 32 + lane];
        acc.x = fmaf(e.x, w.x, acc.x);
        acc.y = fmaf(e.y, w.y, acc.y);
    }
    float ss = acc.x * acc.x + acc.y * acc.y;
    #pragma unroll
    for (int o = 16; o; o >>= 1) ss += __shfl_xor_sync(0xFFFFFFFFu, ss, o);
    float inv = 1.f / fmaxf(sqrtf(ss), 1e-12f);
    acc.x *= inv; acc.y *= inv;
    int idx = gw * 32 + lane;
    enxt[idx] = __floats2half2_rn(acc.x, acc.y);
    float2 o = out_ent[idx];
    o.x += acc.x; o.y += acc.y;
    out_ent[idx] = o;
}

// ---------------------------------------------------------------------------
// user hop: warp-per-user, R13 inner loop verbatim. No s_w smem / no sync.
// ---------------------------------------------------------------------------
__global__ void k_hop_usr(int hop, const float2* __restrict__ user_emb,
                          const float2* __restrict__ latent2,
                          float2* __restrict__ out_usr) {
    int tid = threadIdx.x;
    int gw   = (blockIdx.x * blockDim.x + tid) >> 5;
    int lane = tid & 31;
    if (gw >= N_USERS) return;

    const __half2* ecur = hop ? g_eh1 : g_eh0;

    int bin   = N_ENTITIES + gw;
    int start = g_off[bin];
    int n     = g_off[bin + 1] - start;
    int ustart = start - N_EDGES;

    float2 acc = make_float2(0.f, 0.f);
    #pragma unroll 4
    for (int k = 0; k < n; k++) {
        int2 it = __ldg(&g_uitem[ustart + k]);
        float v = __int_as_float(it.y);
        float2 e = __half22float2(__ldg(&ecur[it.x * 32 + lane]));
        acc.x = fmaf(v, e.x, acc.x);
        acc.y = fmaf(v, e.y, acc.y);
    }
    int idx = gw * 32 + lane;
    float2 uc = hop ? g_un[idx] : user_emb[idx];
    float d[N_FACTORS];
    #pragma unroll
    for (int f = 0; f < N_FACTORS; f++) {
        float2 lf = __ldg(&latent2[f * 32 + lane]);
        float p = uc.x * lf.x + uc.y * lf.y;
        #pragma unroll
        for (int o = 16; o; o >>= 1) p += __shfl_xor_sync(0xFFFFFFFFu, p, o);
        d[f] = p;
    }
    float mx = fmaxf(fmaxf(d[0], d[1]), fmaxf(d[2], d[3]));
    float s[N_FACTORS], sum = 0.f;
    #pragma unroll
    for (int f = 0; f < N_FACTORS; f++) { s[f] = expf(d[f] - mx); sum += s[f]; }
    float invs = 1.f / sum;
    const float2* dw = (const float2*)g_disen;
    float2 mix = make_float2(0.f, 0.f);
    #pragma unroll
    for (int f = 0; f < N_FACTORS; f++) {
        float sf = s[f] * invs;
        float2 w2 = dw[f * 32 + lane];
        mix.x = fmaf(sf, w2.x, mix.x);
        mix.y = fmaf(sf, w2.y, mix.y);
    }
    float2 un = make_float2(acc.x * (mix.x + 1.f), acc.y * (mix.y + 1.f));
    float ss = un.x * un.x + un.y * un.y;
    #pragma unroll
    for (int o = 16; o; o >>= 1) ss += __shfl_xor_sync(0xFFFFFFFFu, ss, o);
    float inv = 1.f / fmaxf(sqrtf(ss), 1e-12f);
    un.x *= inv; un.y *= inv;
    g_un[idx] = un;
    float2 o = out_usr[idx];
    o.x += un.x; o.y += un.y;
    out_usr[idx] = o;
}

// ---------------------------------------------------------------------------
extern "C" void kernel_launch(void* const* d_in, const int* in_sizes, int n_in,
                              void* d_out, int out_size) {
    const float* user_emb   = (const float*)d_in[0];
    const float* entity_emb = (const float*)d_in[1];
    const float* latent_emb = (const float*)d_in[2];
    const float* weight     = (const float*)d_in[3];
    const float* att        = (const float*)d_in[4];
    const float* ivals      = (const float*)d_in[5];
    const int*   head       = (const int*)d_in[6];
    const int*   tail       = (const int*)d_in[7];
    const int*   etype      = (const int*)d_in[8];
    const int*   irows      = (const int*)d_in[9];
    const int*   icols      = (const int*)d_in[10];

    float* out     = (float*)d_out;
    float* out_ent = out;
    float* out_usr = out + (size_t)N_ENTITIES * CHANNEL;
    float* out_cor = out + (size_t)(N_ENTITIES + N_USERS) * CHANNEL;

    const int TPB = 256;
    int init_blocks = (EV4 + UV4 + TPB - 1) / TPB;
    int item_blocks = (NITEMS + TPB - 1) / TPB;

    k_init<<<init_blocks, TPB>>>((const float4*)entity_emb, (const float4*)user_emb,
                                 (float4*)out_ent, (float4*)out_usr);
    k_small<<<1, 256>>>(att, weight, out_cor);

    k_hist<<<item_blocks, TPB>>>(head, irows);
    k_scan1<<<NBLK, CHUNK>>>();
    k_scan3<<<NBLK, CHUNK>>>();
    k_scatter<<<item_blocks, TPB>>>(head, tail, etype, irows, icols, ivals);

    int ent_blocks = (N_ENTITIES * 32 + TPB - 1) / TPB;
    int usr_blocks = (N_USERS * 32 + TPB - 1) / TPB;
    k_hop_ent<<<ent_blocks, TPB>>>(0, weight, nullptr, (float2*)out_ent);
    k_hop_usr<<<usr_blocks, TPB>>>(0, (const float2*)user_emb,
                                   (const float2*)latent_emb, (float2*)out_usr);
    k_hop_ent<<<ent_blocks, TPB>>>(1, weight, nullptr, (float2*)out_ent);
    k_hop_usr<<<usr_blocks, TPB>>>(1, (const float2*)user_emb,
                                   (const float2*)latent_emb, (float2*)out_usr);
}

// round 17
// speedup vs baseline: 1.1112x; 1.0291x over previous
#include <cuda_runtime.h>
#include <cuda_fp16.h>

#define N_USERS    50000
#define N_ENTITIES 100000
#define CHANNEL    64
#define N_FACTORS  4
#define N_RELM1    8
#define N_EDGES    1500000
#define NNZ        800000

#define NBINS   (N_ENTITIES + N_USERS)
#define NITEMS  (N_EDGES + NNZ)
#define CHUNK   1024
#define NBLK    ((NBINS + CHUNK - 1) / CHUNK)   // 147

#define EV4 (N_ENTITIES * 16)
#define UV4 (N_USERS * 16)

// 8 warps per 256-thread block; 2-ent:1-usr interleave
#define ENT_BLOCKS (N_ENTITIES / 8)             // 12500
#define USR_BLOCKS (N_USERS / 8)                // 6250
#define HOP_BLOCKS (ENT_BLOCKS + USR_BLOCKS)    // 18750

// fp16 ping-pong entity tables: one row = 64ch = 32 x half2 = 128B = 1 L2 line
__device__ __half2 g_eh0[N_ENTITIES * 32];
__device__ __half2 g_eh1[N_ENTITIES * 32];
// normalized user rows after hop0 (fp32)
__device__ float2  g_un[N_USERS * 32];
__device__ float   g_disen[N_FACTORS * CHANNEL];

// CSR build (g_cnt zero-initialized; re-zeroed by k_scan3 each replay)
__device__ int   g_cnt[NBINS];
__device__ int   g_off[NBINS + 1];
__device__ int   g_pos[NBINS];
__device__ int   g_bsum[NBLK];
__device__ int   g_ecol[N_EDGES];   // tail | (rel<<20)
__device__ int2  g_uitem[NNZ];      // {col, val bits}

// ---------------------------------------------------------------------------
__global__ void k_init(const float4* __restrict__ ent, const float4* __restrict__ usr,
                       float4* __restrict__ out_ent, float4* __restrict__ out_usr) {
    int i = blockIdx.x * blockDim.x + threadIdx.x;
    if (i < EV4) {
        float4 v = ent[i];
        out_ent[i] = v;
        g_eh0[i * 2 + 0] = __floats2half2_rn(v.x, v.y);
        g_eh0[i * 2 + 1] = __floats2half2_rn(v.z, v.w);
    } else {
        int j = i - EV4;
        if (j < UV4) out_usr[j] = usr[j];
    }
}

// ---------------------------------------------------------------------------
__global__ void k_hist(const int* __restrict__ head, const int* __restrict__ irows) {
    int i = blockIdx.x * blockDim.x + threadIdx.x;
    if (i < N_EDGES) {
        atomicAdd(&g_cnt[head[i]], 1);
    } else if (i < NITEMS) {
        atomicAdd(&g_cnt[N_ENTITIES + irows[i - N_EDGES]], 1);
    }
}

__global__ void k_scan1() {
    __shared__ int s[CHUNK];
    int b = blockIdx.x, t = threadIdx.x;
    int i = b * CHUNK + t;
    s[t] = (i < NBINS) ? g_cnt[i] : 0;
    __syncthreads();
    for (int o = CHUNK >> 1; o; o >>= 1) {
        if (t < o) s[t] += s[t + o];
        __syncthreads();
    }
    if (t == 0) g_bsum[b] = s[0];
}

// per-chunk scan; block base computed inline from g_bsum (scan2 folded in);
// writes offsets + cursors, sentinel, re-zeros g_cnt for the next replay
__global__ void k_scan3() {
    __shared__ int s[CHUNK];
    __shared__ int sb[256];
    int b = blockIdx.x, t = threadIdx.x;

    if (t < 256) sb[t] = (t < NBLK) ? g_bsum[t] : 0;
    __syncthreads();
    for (int o = 1; o < 256; o <<= 1) {
        int x = (t < 256 && t >= o) ? sb[t - o] : 0;
        __syncthreads();
        if (t < 256) sb[t] += x;
        __syncthreads();
    }
    int base = sb[b] - g_bsum[b];

    int i = b * CHUNK + t;
    int v = (i < NBINS) ? g_cnt[i] : 0;
    s[t] = v;
    __syncthreads();
    for (int o = 1; o < CHUNK; o <<= 1) {
        int x = (t >= o) ? s[t - o] : 0;
        __syncthreads();
        s[t] += x;
        __syncthreads();
    }
    if (i < NBINS) {
        int off = base + s[t] - v;
        g_off[i] = off;
        g_pos[i] = off;
        g_cnt[i] = 0;
    }
    if (i == NBINS - 1) g_off[NBINS] = NITEMS;
}

__global__ void k_scatter(const int* __restrict__ head, const int* __restrict__ tail,
                          const int* __restrict__ etype,
                          const int* __restrict__ irows, const int* __restrict__ icols,
                          const float* __restrict__ ivals) {
    int i = blockIdx.x * blockDim.x + threadIdx.x;
    if (i < N_EDGES) {
        int h = head[i];
        int pos = atomicAdd(&g_pos[h], 1);
        g_ecol[pos] = tail[i] | ((etype[i] - 1) << 20);
    } else if (i < NITEMS) {
        int j = i - N_EDGES;
        int r = irows[j];
        int pos = atomicAdd(&g_pos[N_ENTITIES + r], 1) - N_EDGES;
        g_uitem[pos] = make_int2(icols[j], __float_as_int(ivals[j]));
    }
}

// ---------------------------------------------------------------------------
// small kernel: disen = softmax(att) @ W + warp-parallel distance correlation
// ---------------------------------------------------------------------------
__global__ void k_small(const float* __restrict__ att, const float* __restrict__ w,
                        float* __restrict__ out_cor) {
    __shared__ float s_cor[6];
    int t = threadIdx.x;

    if (t < N_FACTORS * CHANNEL) {
        int f = t >> 6, c = t & 63;
        float row[N_RELM1];
        float mx = -1e30f;
        for (int j = 0; j < N_RELM1; j++) { row[j] = att[f * N_RELM1 + j]; mx = fmaxf(mx, row[j]); }
        float s = 0.f;
        for (int j = 0; j < N_RELM1; j++) { row[j] = expf(row[j] - mx); s += row[j]; }
        float invs = 1.f / s;
        float acc = 0.f;
        for (int j = 0; j < N_RELM1; j++) acc += row[j] * invs * w[j * CHANNEL + c];
        g_disen[t] = acc;
    }

    int wid = t >> 5, lane = t & 31;
    if (wid < 6) {
        const int pi_[6] = {0, 0, 0, 1, 1, 2};
        const int pj_[6] = {1, 2, 3, 2, 3, 3};
        int p1 = pi_[wid], p2 = pj_[wid];
        float t1[N_RELM1], t2[N_RELM1];
        #pragma unroll
        for (int k = 0; k < N_RELM1; k++) {
            t1[k] = __ldg(&att[p1 * N_RELM1 + k]);
            t2[k] = __ldg(&att[p2 * N_RELM1 + k]);
        }
        int i1 = lane >> 3, j1 = lane & 7, i2 = i1 + 4;
        float da1 = t1[i1] - t1[j1], da2 = t1[i2] - t1[j1];
        float db1 = t2[i1] - t2[j1], db2 = t2[i2] - t2[j1];
        float a1 = sqrtf(da1 * da1 + 1e-8f), a2 = sqrtf(da2 * da2 + 1e-8f);
        float b1 = sqrtf(db1 * db1 + 1e-8f), b2 = sqrtf(db2 * db2 + 1e-8f);

        float ar1 = a1, ar2 = a2, br1 = b1, br2 = b2;
        #pragma unroll
        for (int o = 1; o <= 4; o <<= 1) {
            ar1 += __shfl_xor_sync(0xFFFFFFFFu, ar1, o);
            ar2 += __shfl_xor_sync(0xFFFFFFFFu, ar2, o);
            br1 += __shfl_xor_sync(0xFFFFFFFFu, br1, o);
            br2 += __shfl_xor_sync(0xFFFFFFFFu, br2, o);
        }
        float ac1 = a1, ac2 = a2, bc1 = b1, bc2 = b2;
        #pragma unroll
        for (int o = 8; o <= 16; o <<= 1) {
            ac1 += __shfl_xor_sync(0xFFFFFFFFu, ac1, o);
            ac2 += __shfl_xor_sync(0xFFFFFFFFu, ac2, o);
            bc1 += __shfl_xor_sync(0xFFFFFFFFu, bc1, o);
            bc2 += __shfl_xor_sync(0xFFFFFFFFu, bc2, o);
        }
        float asum = a1 + a2, bsum = b1 + b2;
        #pragma unroll
        for (int o = 1; o <= 16; o <<= 1) {
            asum += __shfl_xor_sync(0xFFFFFFFFu, asum, o);
            bsum += __shfl_xor_sync(0xFFFFFFFFu, bsum, o);
        }
        float am = asum * (1.f / 64.f), bm = bsum * (1.f / 64.f);
        float acm = (ac1 + ac2) * 0.125f, bcm = (bc1 + bc2) * 0.125f;
        float A1 = a1 - acm - ar1 * 0.125f + am;
        float A2 = a2 - acm - ar2 * 0.125f + am;
        float B1 = b1 - bcm - br1 * 0.125f + bm;
        float B2 = b2 - bcm - br2 * 0.125f + bm;
        float sAB = A1 * B1 + A2 * B2;
        float sAA = A1 * A1 + A2 * A2;
        float sBB = B1 * B1 + B2 * B2;
        #pragma unroll
        for (int o = 1; o <= 16; o <<= 1) {
            sAB += __shfl_xor_sync(0xFFFFFFFFu, sAB, o);
            sAA += __shfl_xor_sync(0xFFFFFFFFu, sAA, o);
            sBB += __shfl_xor_sync(0xFFFFFFFFu, sBB, o);
        }
        if (lane == 0) {
            float dAB = sqrtf(fmaxf(sAB * (1.f / 64.f), 0.f) + 1e-8f);
            float dAA = sqrtf(fmaxf(sAA * (1.f / 64.f), 0.f) + 1e-8f);
            float dBB = sqrtf(fmaxf(sBB * (1.f / 64.f), 0.f) + 1e-8f);
            s_cor[wid] = dAB / sqrtf(dAA * dBB + 1e-8f);
        }
    }
    __syncthreads();
    if (t == 0)
        *out_cor = s_cor[0] + s_cor[1] + s_cor[2] + s_cor[3] + s_cor[4] + s_cor[5];
}

// ---------------------------------------------------------------------------
// fused hop: ONE kernel per hop; blocks interleaved 2-entity : 1-user so user
// work co-schedules with (and hides under) the dominant entity pass. Branch
// is block-uniform; inner loops byte-identical to the measured-best R13/R16.
// ---------------------------------------------------------------------------
__global__ void k_hop(int hop, const float2* __restrict__ user_emb,
                      const float* __restrict__ weight,
                      const float2* __restrict__ latent2,
                      float2* __restrict__ out_ent, float2* __restrict__ out_usr) {
    __shared__ float2 s_w[N_RELM1 * 32];

    int b    = blockIdx.x;
    int tid  = threadIdx.x;
    int lane = tid & 31;
    int bw   = tid >> 5;          // warp in block (0..7)
    int r3   = b % 3;
    int grp  = b / 3;

    const __half2* ecur = hop ? g_eh1 : g_eh0;

    if (r3 < 2) {
        // ---------------- entity block ----------------
        __half2* enxt = hop ? g_eh0 : g_eh1;
        for (int i = tid; i < N_RELM1 * 32; i += blockDim.x)
            s_w[i] = ((const float2*)weight)[i];
        __syncthreads();

        int gw = (grp * 2 + r3) * 8 + bw;
        if (gw >= N_ENTITIES) return;

        int start = g_off[gw];
        int n     = g_off[gw + 1] - start;

        float2 acc = make_float2(0.f, 0.f);
        #pragma unroll 4
        for (int k = 0; k < n; k++) {
            int p = __ldg(&g_ecol[start + k]);
            int t = p & 0xFFFFF;
            int r = p >> 20;
            float2 e = __half22float2(__ldg(&ecur[t * 32 + lane]));
            float2 w = s_w[r * 32 + lane];
            acc.x = fmaf(e.x, w.x, acc.x);
            acc.y = fmaf(e.y, w.y, acc.y);
        }
        float ss = acc.x * acc.x + acc.y * acc.y;
        #pragma unroll
        for (int o = 16; o; o >>= 1) ss += __shfl_xor_sync(0xFFFFFFFFu, ss, o);
        float inv = 1.f / fmaxf(sqrtf(ss), 1e-12f);
        acc.x *= inv; acc.y *= inv;
        int idx = gw * 32 + lane;
        enxt[idx] = __floats2half2_rn(acc.x, acc.y);
        float2 o = out_ent[idx];
        o.x += acc.x; o.y += acc.y;
        out_ent[idx] = o;
    } else {
        // ---------------- user block ----------------
        int gw = grp * 8 + bw;
        if (gw >= N_USERS) return;

        int bin    = N_ENTITIES + gw;
        int start  = g_off[bin];
        int n      = g_off[bin + 1] - start;
        int ustart = start - N_EDGES;

        float2 acc = make_float2(0.f, 0.f);
        #pragma unroll 4
        for (int k = 0; k < n; k++) {
            int2 it = __ldg(&g_uitem[ustart + k]);
            float v = __int_as_float(it.y);
            float2 e = __half22float2(__ldg(&ecur[it.x * 32 + lane]));
            acc.x = fmaf(v, e.x, acc.x);
            acc.y = fmaf(v, e.y, acc.y);
        }
        int idx = gw * 32 + lane;
        float2 uc = hop ? g_un[idx] : user_emb[idx];
        float d[N_FACTORS];
        #pragma unroll
        for (int f = 0; f < N_FACTORS; f++) {
            float2 lf = __ldg(&latent2[f * 32 + lane]);
            float p = uc.x * lf.x + uc.y * lf.y;
            #pragma unroll
            for (int o = 16; o; o >>= 1) p += __shfl_xor_sync(0xFFFFFFFFu, p, o);
            d[f] = p;
        }
        float mx = fmaxf(fmaxf(d[0], d[1]), fmaxf(d[2], d[3]));
        float s[N_FACTORS], sum = 0.f;
        #pragma unroll
        for (int f = 0; f < N_FACTORS; f++) { s[f] = expf(d[f] - mx); sum += s[f]; }
        float invs = 1.f / sum;
        const float2* dw = (const float2*)g_disen;
        float2 mix = make_float2(0.f, 0.f);
        #pragma unroll
        for (int f = 0; f < N_FACTORS; f++) {
            float sf = s[f] * invs;
            float2 w2 = dw[f * 32 + lane];
            mix.x = fmaf(sf, w2.x, mix.x);
            mix.y = fmaf(sf, w2.y, mix.y);
        }
        float2 un = make_float2(acc.x * (mix.x + 1.f), acc.y * (mix.y + 1.f));
        float ss = un.x * un.x + un.y * un.y;
        #pragma unroll
        for (int o = 16; o; o >>= 1) ss += __shfl_xor_sync(0xFFFFFFFFu, ss, o);
        float inv = 1.f / fmaxf(sqrtf(ss), 1e-12f);
        un.x *= inv; un.y *= inv;
        g_un[idx] = un;
        float2 o = out_usr[idx];
        o.x += un.x; o.y += un.y;
        out_usr[idx] = o;
    }
}

// ---------------------------------------------------------------------------
extern "C" void kernel_launch(void* const* d_in, const int* in_sizes, int n_in,
                              void* d_out, int out_size) {
    const float* user_emb   = (const float*)d_in[0];
    const float* entity_emb = (const float*)d_in[1];
    const float* latent_emb = (const float*)d_in[2];
    const float* weight     = (const float*)d_in[3];
    const float* att        = (const float*)d_in[4];
    const float* ivals      = (const float*)d_in[5];
    const int*   head       = (const int*)d_in[6];
    const int*   tail       = (const int*)d_in[7];
    const int*   etype      = (const int*)d_in[8];
    const int*   irows      = (const int*)d_in[9];
    const int*   icols      = (const int*)d_in[10];

    float* out     = (float*)d_out;
    float* out_ent = out;
    float* out_usr = out + (size_t)N_ENTITIES * CHANNEL;
    float* out_cor = out + (size_t)(N_ENTITIES + N_USERS) * CHANNEL;

    const int TPB = 256;
    int init_blocks = (EV4 + UV4 + TPB - 1) / TPB;
    int item_blocks = (NITEMS + TPB - 1) / TPB;

    k_init<<<init_blocks, TPB>>>((const float4*)entity_emb, (const float4*)user_emb,
                                 (float4*)out_ent, (float4*)out_usr);
    k_small<<<1, 256>>>(att, weight, out_cor);

    k_hist<<<item_blocks, TPB>>>(head, irows);
    k_scan1<<<NBLK, CHUNK>>>();
    k_scan3<<<NBLK, CHUNK>>>();
    k_scatter<<<item_blocks, TPB>>>(head, tail, etype, irows, icols, ivals);

    k_hop<<<HOP_BLOCKS, TPB>>>(0, (const float2*)user_emb, weight,
                               (const float2*)latent_emb,
                               (float2*)out_ent, (float2*)out_usr);
    k_hop<<<HOP_BLOCKS, TPB>>>(1, (const float2*)user_emb, weight,
                               (const float2*)latent_emb,
                               (float2*)out_ent, (float2*)out_usr);
}